// round 13
// baseline (speedup 1.0000x reference)
#include <cuda_runtime.h>
#include <cuda_bf16.h>
#include <cstdint>

#define N_ALPHA 0.05f
#define N_BETA  0.95f
#define BC_TOT  128
#define NN      1024
#define HID     20
#define KCH     32            // K per chunk
#define NCHUNK  (NN / KCH)    // 32
#define TM      128           // rows per CTA

// A staged RAW fp32: 128 rows x 32 fp32, rows padded to 160B.
// B staged as bf16 hi/lo, 80B rows (conflict-free for ldmatrix).
#define A_RAW   (128 * 160)   // 20480 B
#define B_T     (32 * 80)     // 2560 B
#define OFF_AR  0
#define OFF_BH  A_RAW
#define OFF_BL  (A_RAW + B_T)
#define STAGE   (A_RAW + 2 * B_T)     // 25600
#define NSTG    3
#define SMEM_SZ (NSTG * STAGE)        // 76800

// scratch: h0..h3
__device__ float g_h[4][BC_TOT * NN * HID];

static __device__ __forceinline__ unsigned smem_u32(const void* p) {
    unsigned a;
    asm("{ .reg .u64 t; cvta.to.shared.u64 t, %1; cvt.u32.u64 %0, t; }"
        : "=r"(a) : "l"(p));
    return a;
}
static __device__ __forceinline__ void cp16(unsigned dst, const void* src) {
    asm volatile("cp.async.cg.shared.global [%0], [%1], 16;" :: "r"(dst), "l"(src));
}
static __device__ __forceinline__ unsigned long long fma2(unsigned long long a,
                                                          unsigned long long b,
                                                          unsigned long long c) {
    unsigned long long d;
    asm("fma.rn.f32x2 %0, %1, %2, %3;" : "=l"(d) : "l"(a), "l"(b), "l"(c));
    return d;
}
static __device__ __forceinline__ unsigned long long pack2(float x, float y) {
    unsigned long long d;
    asm("mov.b64 %0, {%1, %2};" : "=l"(d) : "f"(x), "f"(y));
    return d;
}
static __device__ __forceinline__ float2 unpack2(unsigned long long v) {
    float2 f;
    asm("mov.b64 {%0, %1}, %2;" : "=f"(f.x), "=f"(f.y) : "l"(v));
    return f;
}
static __device__ __forceinline__ float2 lds64(uint32_t addr) {
    float2 v;
    asm volatile("ld.shared.v2.f32 {%0,%1}, [%2];"
                 : "=f"(v.x), "=f"(v.y) : "r"(addr));
    return v;
}
static __device__ __forceinline__ void ldm_x2t(uint32_t* r, uint32_t addr) {
    asm volatile("ldmatrix.sync.aligned.m8n8.x2.trans.shared.b16 {%0,%1}, [%2];"
                 : "=r"(r[0]), "=r"(r[1]) : "r"(addr));
}
static __device__ __forceinline__ void mma_bf16(float* c, const uint32_t* a,
                                                const uint32_t* b) {
    asm volatile(
        "mma.sync.aligned.m16n8k16.row.col.f32.bf16.bf16.f32 "
        "{%0,%1,%2,%3}, {%4,%5,%6,%7}, {%8,%9}, {%0,%1,%2,%3};"
        : "+f"(c[0]), "+f"(c[1]), "+f"(c[2]), "+f"(c[3])
        : "r"(a[0]), "r"(a[1]), "r"(a[2]), "r"(a[3]), "r"(b[0]), "r"(b[1]));
}
// hi = truncate-to-bf16 pair; lo = exact residual rounded to bf16 pair
static __device__ __forceinline__ void split2(float x, float y,
                                              uint32_t& hp, uint32_t& lp) {
    uint32_t u0 = __float_as_uint(x), u1 = __float_as_uint(y);
    asm("prmt.b32 %0, %1, %2, 0x7632;" : "=r"(hp) : "r"(u0), "r"(u1));
    float l0 = x - __uint_as_float(u0 & 0xFFFF0000u);
    float l1 = y - __uint_as_float(u1 & 0xFFFF0000u);
    asm("cvt.rn.bf16x2.f32 %0, %1, %2;" : "=r"(lp) : "f"(l1), "f"(l0));
}

// ---------------------------------------------------------------------------
// h0[bc][n][j] = sum_i x[b][i][n][c] * Ws[i][j] + bs[j]
// ---------------------------------------------------------------------------
__global__ void h0_kernel(const float* __restrict__ x,
                          const float* __restrict__ Ws,
                          const float* __restrict__ bs) {
    __shared__ float wsm[32 * HID];
    __shared__ float bsm[HID];
    int tid = threadIdx.x;
    for (int i = tid; i < 32 * HID; i += 256) wsm[i] = Ws[i];
    if (tid < HID) bsm[tid] = bs[tid];
    __syncthreads();

    int r = blockIdx.x * 256 + tid;
    int c = r & 15;
    int n = (r >> 4) & 1023;
    int b = r >> 14;

    unsigned long long acc[10];
    const unsigned long long* bp = (const unsigned long long*)bsm;
#pragma unroll
    for (int j = 0; j < 10; j++) acc[j] = bp[j];

    const float* xp = x + (size_t)b * 32 * 16384 + n * 16 + c;
#pragma unroll
    for (int i = 0; i < 32; i++) {
        float xv = xp[(size_t)i * 16384];
        unsigned long long xv2 = pack2(xv, xv);
        const unsigned long long* wr = (const unsigned long long*)&wsm[i * HID];
#pragma unroll
        for (int j = 0; j < 10; j++) acc[j] = fma2(xv2, wr[j], acc[j]);
    }
    int bc = b * 16 + c;
    float* o = &g_h[0][((size_t)bc * NN + n) * HID];
#pragma unroll
    for (int j = 0; j < 10; j++) {
        float2 f = unpack2(acc[j]);
        o[2 * j] = f.x; o[2 * j + 1] = f.y;
    }
}

// ---------------------------------------------------------------------------
// propagation via mma.sync (bf16 hi/lo emulated fp32), 3-stage cp.async
// pipeline (2 chunks always in flight -> DRAM latency off critical path).
//   iter i: wait(chunk i), sync, issue chunk i+2 -> stage (i+2)%3,
//           STS B chunk i+2 from regs, LDG B chunk i+3 -> regs,
//           compute chunk i from stage i%3.
//   D[v][n<20] = sum_w adj[v][w] h[w][n] ; D[v][20] = rowsum (ones col)
//   h_dst[v] = alpha*h0[v] + beta*(D[v][:20] + h_src[v]) / (D[v][20] + 1)
// ---------------------------------------------------------------------------
__global__ void __launch_bounds__(256, 3)
prop_mma(const float* __restrict__ adj, int src, int dst) {
    extern __shared__ char smem[];
    const uint32_t sb = smem_u32(smem);
    int tid = threadIdx.x;
    int lane = tid & 31, wid = tid >> 5;
    int rowbase = blockIdx.x * TM;
    int bc = blockIdx.y;

    const float* A = adj + ((size_t)bc << 20) + ((size_t)rowbase << 10);
    const float* H = &g_h[src][(size_t)bc * (NN * HID)];

    // zero B regions of all stages; ones col n=20 (byte 40) in each Bhi
    for (int st = 0; st < NSTG; st++) {
        uint32_t* bb = (uint32_t*)(smem + st * STAGE + OFF_BH);
        for (int i = tid; i < (2 * B_T) / 4; i += 256) bb[i] = 0;
    }
    __syncthreads();
    if (tid < 32) {
#pragma unroll
        for (int st = 0; st < NSTG; st++)
            *(uint16_t*)(smem + st * STAGE + OFF_BH + tid * 80 + 40) = 0x3F80;
    }

    bool hasb = tid < 160;
    int bk = tid / 5, bc4 = (tid % 5) * 4;
    uint32_t boff = (uint32_t)bk * 80 + (uint32_t)bc4 * 2;

    float acc[3][4];
#pragma unroll
    for (int nt = 0; nt < 3; nt++)
#pragma unroll
        for (int q = 0; q < 4; q++) acc[nt][q] = 0.f;

    // ---- preamble: A chunks 0,1 via cp.async -> stages 0,1 (2 groups);
    //      B0,B1 split+STS; B2 -> regs
#pragma unroll
    for (int p = 0; p < 4; p++) {
        int g = tid + p * 256;               // 1024 granules of 16B
        int row = g >> 3, q = g & 7;
        cp16(sb + OFF_AR + (uint32_t)row * 160 + (uint32_t)q * 16,
             A + (size_t)row * NN + q * 4);
    }
    asm volatile("cp.async.commit_group;");
#pragma unroll
    for (int p = 0; p < 4; p++) {
        int g = tid + p * 256;
        int row = g >> 3, q = g & 7;
        cp16(sb + STAGE + OFF_AR + (uint32_t)row * 160 + (uint32_t)q * 16,
             A + KCH + (size_t)row * NN + q * 4);
    }
    asm volatile("cp.async.commit_group;");

    float4 bbuf;
    if (hasb) {
#pragma unroll
        for (int cidx = 0; cidx < 2; cidx++) {
            float4 bv = *(const float4*)(H + (size_t)(cidx * KCH + bk) * HID + bc4);
            uint32_t hp0, lp0, hp1, lp1;
            split2(bv.x, bv.y, hp0, lp0);
            split2(bv.z, bv.w, hp1, lp1);
            *(uint2*)(smem + cidx * STAGE + OFF_BH + boff) = make_uint2(hp0, hp1);
            *(uint2*)(smem + cidx * STAGE + OFF_BL + boff) = make_uint2(lp0, lp1);
        }
        bbuf = *(const float4*)(H + (size_t)(2 * KCH + bk) * HID + bc4);
    }

    const uint32_t a_frag_base = (uint32_t)(wid * 16 + (lane >> 2)) * 160 +
                                 (uint32_t)((lane & 3) * 2) * 4;
    const uint32_t b_lm_base = (uint32_t)(lane & 15) * 80;

    int st = 0, wst = 2;     // compute stage, write stage (i%3, (i+2)%3)

#pragma unroll 1
    for (int i = 0; i < NCHUNK; i++) {
        uint32_t stb = sb + st * STAGE;

        if (i + 1 < NCHUNK)
            asm volatile("cp.async.wait_group 1;");   // chunk i arrived
        else
            asm volatile("cp.async.wait_group 0;");
        __syncthreads();   // stage wst free (its readers ran in iter i-1)

        if (i + 2 < NCHUNK) {
            // A chunk i+2 -> stage wst (async)
            const float* ap = A + (i + 2) * KCH;
            uint32_t wb = sb + wst * STAGE;
#pragma unroll
            for (int p = 0; p < 4; p++) {
                int g = tid + p * 256;
                int row = g >> 3, q = g & 7;
                cp16(wb + OFF_AR + (uint32_t)row * 160 + (uint32_t)q * 16,
                     ap + (size_t)row * NN + q * 4);
            }
            asm volatile("cp.async.commit_group;");
            // B chunk i+2 -> stage wst (from regs), prefetch B chunk i+3
            if (hasb) {
                uint32_t hp0, lp0, hp1, lp1;
                split2(bbuf.x, bbuf.y, hp0, lp0);
                split2(bbuf.z, bbuf.w, hp1, lp1);
                *(uint2*)(smem + wst * STAGE + OFF_BH + boff) = make_uint2(hp0, hp1);
                *(uint2*)(smem + wst * STAGE + OFF_BL + boff) = make_uint2(lp0, lp1);
                if (i + 3 < NCHUNK)
                    bbuf = *(const float4*)(H + (size_t)((i + 3) * KCH + bk) * HID + bc4);
            }
        }

        // ---- consume stage st: LDS.64 raw A -> split -> frags; B via ldmatrix
#pragma unroll
        for (int s = 0; s < 2; s++) {
            uint32_t abase = stb + OFF_AR + a_frag_base + (uint32_t)(s * 16) * 4;
            float2 f00 = lds64(abase);
            float2 f10 = lds64(abase + 8 * 160);
            float2 f01 = lds64(abase + 8 * 4);
            float2 f11 = lds64(abase + 8 * 160 + 8 * 4);
            uint32_t ah[4], al[4];
            split2(f00.x, f00.y, ah[0], al[0]);
            split2(f10.x, f10.y, ah[1], al[1]);
            split2(f01.x, f01.y, ah[2], al[2]);
            split2(f11.x, f11.y, ah[3], al[3]);
            uint32_t brow = stb + OFF_BH + b_lm_base + (uint32_t)(s * 16) * 80;
#pragma unroll
            for (int nt = 0; nt < 3; nt++) {
                uint32_t bh[2], bl[2];
                ldm_x2t(bh, brow + nt * 16);
                ldm_x2t(bl, brow + nt * 16 + B_T);
                mma_bf16(acc[nt], ah, bh);
                mma_bf16(acc[nt], ah, bl);
                mma_bf16(acc[nt], al, bh);
            }
        }

        st = (st == NSTG - 1) ? 0 : st + 1;
        wst = (wst == NSTG - 1) ? 0 : wst + 1;
    }

    // ---- epilogue: D frags -> smem (rows padded to 112B), then combine
    __syncthreads();
    {
        char* darea = smem + wid * (16 * 112);
        int r0 = lane >> 2;
        int cb = (lane & 3) * 2;
#pragma unroll
        for (int nt = 0; nt < 3; nt++) {
            int cbyte = (nt * 8 + cb) * 4;
            *(float2*)(darea + r0 * 112 + cbyte) = make_float2(acc[nt][0], acc[nt][1]);
            *(float2*)(darea + (r0 + 8) * 112 + cbyte) = make_float2(acc[nt][2], acc[nt][3]);
        }
    }
    __syncthreads();
    if (tid < TM) {
        const float* Drow = (const float*)(smem + (tid >> 4) * (16 * 112) +
                                           (tid & 15) * 112);
        int v = rowbase + tid;
        float ir = 1.f / (Drow[20] + 1.f);
        const float* hsr = H + (size_t)v * HID;
        const float* h0r = &g_h[0][(size_t)bc * (NN * HID) + (size_t)v * HID];
        float* outr = &g_h[dst][(size_t)bc * (NN * HID) + (size_t)v * HID];
        float res[20];
#pragma unroll
        for (int j = 0; j < 20; j++)
            res[j] = N_ALPHA * h0r[j] + N_BETA * (Drow[j] + hsr[j]) * ir;
#pragma unroll
        for (int q = 0; q < 5; q++)
            ((float4*)outr)[q] = make_float4(res[4 * q], res[4 * q + 1],
                                             res[4 * q + 2], res[4 * q + 3]);
    }
}

// ---------------------------------------------------------------------------
// out[bc][n][o] = sum_{p,j} h_p[bc][n][j] * We[(p*20+j)][o] + be[o]
// ---------------------------------------------------------------------------
__global__ void __launch_bounds__(256) end_kernel(const float* __restrict__ We,
                                                  const float* __restrict__ be,
                                                  float* __restrict__ out) {
    __shared__ float wsm[80 * 32];
    __shared__ float bsm[32];
    __shared__ float hsm[256 * HID];
    int tid = threadIdx.x;
    for (int i = tid; i < 80 * 32; i += 256) wsm[i] = We[i];
    if (tid < 32) bsm[tid] = be[tid];

    int r0 = blockIdx.x * 256;

    unsigned long long acc[16];
    const unsigned long long* bp = (const unsigned long long*)bsm;
#pragma unroll
    for (int p = 0; p < 4; p++) {
        __syncthreads();
        const float4* src4 = (const float4*)(&g_h[p][0] + (size_t)r0 * HID);
#pragma unroll
        for (int k = 0; k < 5; k++)
            ((float4*)hsm)[tid + k * 256] = src4[tid + k * 256];
        __syncthreads();
        if (p == 0) {
#pragma unroll
            for (int o = 0; o < 16; o++) acc[o] = bp[o];
        }
        const float* hr = hsm + tid * HID;
#pragma unroll
        for (int j = 0; j < HID; j++) {
            float v = hr[j];
            unsigned long long v2 = pack2(v, v);
            const unsigned long long* wr =
                (const unsigned long long*)&wsm[(p * HID + j) * 32];
#pragma unroll
            for (int o = 0; o < 16; o++) acc[o] = fma2(v2, wr[o], acc[o]);
        }
    }

    float* op = out + ((size_t)r0 + tid) * 32;
#pragma unroll
    for (int o = 0; o < 16; o++) {
        float2 f = unpack2(acc[o]);
        op[2 * o] = f.x; op[2 * o + 1] = f.y;
    }
}

// ---------------------------------------------------------------------------
extern "C" void kernel_launch(void* const* d_in, const int* in_sizes, int n_in,
                              void* d_out, int out_size) {
    const float* x   = (const float*)d_in[0];
    const float* adj = (const float*)d_in[1];
    const float* Ws  = (const float*)d_in[2];
    const float* bs  = (const float*)d_in[3];
    const float* We  = (const float*)d_in[4];
    const float* be  = (const float*)d_in[5];
    float* out = (float*)d_out;

    cudaFuncSetAttribute(prop_mma, cudaFuncAttributeMaxDynamicSharedMemorySize,
                         SMEM_SZ);

    dim3 pgrid(NN / TM, BC_TOT);   // (8, 128) = 1024 CTAs

    h0_kernel<<<512, 256>>>(x, Ws, bs);
    prop_mma<<<pgrid, 256, SMEM_SZ>>>(adj, 0, 1);
    prop_mma<<<pgrid, 256, SMEM_SZ>>>(adj, 1, 2);
    prop_mma<<<pgrid, 256, SMEM_SZ>>>(adj, 2, 3);
    end_kernel<<<512, 256>>>(We, be, out);
}